// round 15
// baseline (speedup 1.0000x reference)
#include <cuda_runtime.h>

#define BB 256
#define TT 2048
#define HH 128
#define FC1N 64
#define RING 32          // ring depth (steps per FC chunk)
#define RPAD 132         // floats per ring row (16B-aligned, 4-way FC conflict)

__device__ __forceinline__ unsigned long long fma2(unsigned long long a,
                                                   unsigned long long b,
                                                   unsigned long long c) {
    unsigned long long d;
    asm("fma.rn.f32x2 %0, %1, %2, %3;" : "=l"(d) : "l"(a), "l"(b), "l"(c));
    return d;
}
__device__ __forceinline__ unsigned long long add2(unsigned long long a,
                                                   unsigned long long b) {
    unsigned long long d;
    asm("add.rn.f32x2 %0, %1, %2;" : "=l"(d) : "l"(a), "l"(b));
    return d;
}
__device__ __forceinline__ float2 unpack2(unsigned long long v) {
    float2 r;
    asm("mov.b64 {%0, %1}, %2;" : "=f"(r.x), "=f"(r.y) : "l"(v));
    return r;
}
__device__ __forceinline__ float tanh_fast(float x) {
    float y;
    asm("tanh.approx.f32 %0, %1;" : "=f"(y) : "f"(x));
    return y;
}

__global__ __launch_bounds__(128, 2)
void rnn_fused_kernel(const float* __restrict__ x,
                      const float* __restrict__ hidden,
                      const float* __restrict__ W_ih,
                      const float* __restrict__ W_hh,
                      const float* __restrict__ b_ih,
                      const float* __restrict__ b_hh,
                      const float* __restrict__ W_fc1,
                      const float* __restrict__ b_fc1,
                      const float* __restrict__ W_fc2,
                      const float* __restrict__ b_fc2,
                      float* __restrict__ out)
{
    __shared__ __align__(16) float x_sh[TT * 3];            // 24 KB
    __shared__ __align__(16) float h_ring[RING * RPAD];     // 16.5 KB
    __shared__ __align__(16) float wc_sh[3][HH];            // collapsed fc2@fc1
    __shared__ float part_sh[4][RING * 3];                  // FC partials
    __shared__ float bc_sh[3];

    const int b = blockIdx.x;
    const int j = threadIdx.x;          // hidden unit owned by this thread

    // ---- preload x[b] into SMEM (coalesced float4, 12 iters) ----
    {
        const float4* xg = (const float4*)(x + (size_t)b * TT * 3);
        float4* xs = (float4*)x_sh;
        #pragma unroll
        for (int i = 0; i < (TT * 3 / 4) / HH; i++)
            xs[i * HH + j] = xg[i * HH + j];
    }

    // ---- W_hh row j into registers as packed f32x2 (64 ull regs) ----
    unsigned long long w[HH / 2];
    {
        const unsigned long long* wg = (const unsigned long long*)(W_hh + j * HH);
        #pragma unroll
        for (int i = 0; i < HH / 2; i++) w[i] = wg[i];
    }

    const float wih0 = W_ih[j * 3 + 0];
    const float wih1 = W_ih[j * 3 + 1];
    const float wih2 = W_ih[j * 3 + 2];
    const float bias = b_ih[j] + b_hh[j];

    // ---- collapse FC head: wc[o][j] = sum_f W_fc2[o][f] * W_fc1[f][j] ----
    {
        float wc0 = 0.f, wc1 = 0.f, wc2 = 0.f;
        #pragma unroll 4
        for (int f = 0; f < FC1N; f++) {
            float v = W_fc1[f * HH + j];
            wc0 = fmaf(W_fc2[0 * FC1N + f], v, wc0);
            wc1 = fmaf(W_fc2[1 * FC1N + f], v, wc1);
            wc2 = fmaf(W_fc2[2 * FC1N + f], v, wc2);
        }
        wc_sh[0][j] = wc0; wc_sh[1][j] = wc1; wc_sh[2][j] = wc2;
    }
    if (j < 3) {
        float s = 0.f;
        #pragma unroll 8
        for (int f = 0; f < FC1N; f++)
            s = fmaf(W_fc2[j * FC1N + f], b_fc1[f], s);
        bc_sh[j] = s + b_fc2[j];
    }

    // ---- initial hidden state lives in slot RING-1 (t = -1) ----
    h_ring[(RING - 1) * RPAD + j] = hidden[b * HH + j];
    __syncthreads();

    const int kg = j >> 5;        // FC k-group (0..3)
    const int tl = j & 31;        // FC local timestep
    float* outb = out + (size_t)b * TT * 3;

    float hv = 0.f;
    for (int t = 0; t < TT; t++) {
        // x projection (independent of h — schedule first)
        const float xv0 = x_sh[3 * t + 0];
        const float xv1 = x_sh[3 * t + 1];
        const float xv2 = x_sh[3 * t + 2];
        float xp = fmaf(xv2, wih2, fmaf(xv1, wih1, fmaf(xv0, wih0, bias)));

        // 128-wide dot(W_j, h_prev): 8 chains x 8 packed FMAs (broadcast LDS)
        // 8 shallow chains halve the end-of-dot drain depth vs 4x16.
        const ulonglong2* hp =
            (const ulonglong2*)(h_ring + ((t - 1) & (RING - 1)) * RPAD);
        unsigned long long a0 = 0ull, a1 = 0ull, a2 = 0ull, a3 = 0ull;
        unsigned long long a4 = 0ull, a5 = 0ull, a6 = 0ull, a7 = 0ull;
        #pragma unroll
        for (int i = 0; i < 8; i++) {
            ulonglong2 ha = hp[4 * i + 0];
            ulonglong2 hb = hp[4 * i + 1];
            ulonglong2 hc = hp[4 * i + 2];
            ulonglong2 hd = hp[4 * i + 3];
            a0 = fma2(w[8 * i + 0], ha.x, a0);
            a1 = fma2(w[8 * i + 1], ha.y, a1);
            a2 = fma2(w[8 * i + 2], hb.x, a2);
            a3 = fma2(w[8 * i + 3], hb.y, a3);
            a4 = fma2(w[8 * i + 4], hc.x, a4);
            a5 = fma2(w[8 * i + 5], hc.y, a5);
            a6 = fma2(w[8 * i + 6], hd.x, a6);
            a7 = fma2(w[8 * i + 7], hd.y, a7);
        }
        unsigned long long s2 = add2(add2(add2(a0, a1), add2(a2, a3)),
                                     add2(add2(a4, a5), add2(a6, a7)));
        float2 f = unpack2(s2);

        hv = tanh_fast(xp + (f.x + f.y));
        h_ring[(t & (RING - 1)) * RPAD + j] = hv;
        __syncthreads();

        // ---- amortized FC head: every RING steps, drain slots 0..31 ----
        if ((t & (RING - 1)) == (RING - 1)) {
            const float4* h4 = (const float4*)(h_ring + tl * RPAD + kg * 32);
            const float4* w0 = (const float4*)(wc_sh[0] + kg * 32);
            const float4* w1 = (const float4*)(wc_sh[1] + kg * 32);
            const float4* w2 = (const float4*)(wc_sh[2] + kg * 32);
            float p0 = 0.f, p1 = 0.f, p2 = 0.f;
            #pragma unroll
            for (int i = 0; i < 8; i++) {
                float4 hq = h4[i];
                float4 wa = w0[i], wb = w1[i], wcc = w2[i];
                p0 = fmaf(hq.x, wa.x, fmaf(hq.y, wa.y, fmaf(hq.z, wa.z, fmaf(hq.w, wa.w, p0))));
                p1 = fmaf(hq.x, wb.x, fmaf(hq.y, wb.y, fmaf(hq.z, wb.z, fmaf(hq.w, wb.w, p1))));
                p2 = fmaf(hq.x, wcc.x, fmaf(hq.y, wcc.y, fmaf(hq.z, wcc.z, fmaf(hq.w, wcc.w, p2))));
            }
            part_sh[kg][tl * 3 + 0] = p0;
            part_sh[kg][tl * 3 + 1] = p1;
            part_sh[kg][tl * 3 + 2] = p2;
            __syncthreads();

            if (j < RING * 3) {
                float v = part_sh[0][j] + part_sh[1][j] +
                          part_sh[2][j] + part_sh[3][j] + bc_sh[j % 3];
                outb[(size_t)(t - (RING - 1)) * 3 + j] = v;   // 96 coalesced floats
            }
            // ring slot 0 is rewritten only after the next step's barrier;
            // partials are rewritten only after 32 more barriers. No extra sync.
        }
    }

    // final hidden state -> second output region
    out[(size_t)BB * TT * 3 + b * HH + j] = hv;
}

extern "C" void kernel_launch(void* const* d_in, const int* in_sizes, int n_in,
                              void* d_out, int out_size) {
    const float* x      = (const float*)d_in[0];
    const float* hidden = (const float*)d_in[1];
    const float* W_ih   = (const float*)d_in[2];
    const float* W_hh   = (const float*)d_in[3];
    const float* b_ih   = (const float*)d_in[4];
    const float* b_hh   = (const float*)d_in[5];
    const float* W_fc1  = (const float*)d_in[6];
    const float* b_fc1  = (const float*)d_in[7];
    const float* W_fc2  = (const float*)d_in[8];
    const float* b_fc2  = (const float*)d_in[9];
    float* out = (float*)d_out;

    rnn_fused_kernel<<<BB, HH>>>(x, hidden, W_ih, W_hh, b_ih, b_hh,
                                 W_fc1, b_fc1, W_fc2, b_fc2, out);
}

// round 16
// speedup vs baseline: 1.0827x; 1.0827x over previous
#include <cuda_runtime.h>

#define BB 256
#define TT 2048
#define HH 128
#define FC1N 64
#define RING 32          // ring depth (steps per FC chunk)
#define RPAD 132         // floats per ring row (132: 16B-aligned, 4-way FC conflict)

__device__ __forceinline__ unsigned long long fma2(unsigned long long a,
                                                   unsigned long long b,
                                                   unsigned long long c) {
    unsigned long long d;
    asm("fma.rn.f32x2 %0, %1, %2, %3;" : "=l"(d) : "l"(a), "l"(b), "l"(c));
    return d;
}
__device__ __forceinline__ unsigned long long add2(unsigned long long a,
                                                   unsigned long long b) {
    unsigned long long d;
    asm("add.rn.f32x2 %0, %1, %2;" : "=l"(d) : "l"(a), "l"(b));
    return d;
}
__device__ __forceinline__ float2 unpack2(unsigned long long v) {
    float2 r;
    asm("mov.b64 {%0, %1}, %2;" : "=f"(r.x), "=f"(r.y) : "l"(v));
    return r;
}
__device__ __forceinline__ float tanh_fast(float x) {
    float y;
    asm("tanh.approx.f32 %0, %1;" : "=f"(y) : "f"(x));
    return y;
}

__global__ __launch_bounds__(128, 2)
void rnn_fused_kernel(const float* __restrict__ x,
                      const float* __restrict__ hidden,
                      const float* __restrict__ W_ih,
                      const float* __restrict__ W_hh,
                      const float* __restrict__ b_ih,
                      const float* __restrict__ b_hh,
                      const float* __restrict__ W_fc1,
                      const float* __restrict__ b_fc1,
                      const float* __restrict__ W_fc2,
                      const float* __restrict__ b_fc2,
                      float* __restrict__ out)
{
    __shared__ __align__(16) float x_sh[TT * 3];            // 24 KB
    __shared__ __align__(16) float h_ring[RING * RPAD];     // 16.5 KB
    __shared__ __align__(16) float wc_sh[3][HH];            // collapsed fc2@fc1
    __shared__ float part_sh[4][RING * 3];                  // FC partials
    __shared__ float bc_sh[3];

    const int b = blockIdx.x;
    const int j = threadIdx.x;          // hidden unit owned by this thread

    // ---- preload x[b] into SMEM (coalesced float4, 12 iters) ----
    {
        const float4* xg = (const float4*)(x + (size_t)b * TT * 3);
        float4* xs = (float4*)x_sh;
        #pragma unroll
        for (int i = 0; i < (TT * 3 / 4) / HH; i++)
            xs[i * HH + j] = xg[i * HH + j];
    }

    // ---- W_hh row j into registers as packed f32x2 (64 ull regs) ----
    unsigned long long w[HH / 2];
    {
        const unsigned long long* wg = (const unsigned long long*)(W_hh + j * HH);
        #pragma unroll
        for (int i = 0; i < HH / 2; i++) w[i] = wg[i];
    }

    const float wih0 = W_ih[j * 3 + 0];
    const float wih1 = W_ih[j * 3 + 1];
    const float wih2 = W_ih[j * 3 + 2];
    const float bias = b_ih[j] + b_hh[j];

    // ---- collapse FC head: wc[o][j] = sum_f W_fc2[o][f] * W_fc1[f][j] ----
    {
        float wc0 = 0.f, wc1 = 0.f, wc2 = 0.f;
        #pragma unroll 4
        for (int f = 0; f < FC1N; f++) {
            float v = W_fc1[f * HH + j];
            wc0 = fmaf(W_fc2[0 * FC1N + f], v, wc0);
            wc1 = fmaf(W_fc2[1 * FC1N + f], v, wc1);
            wc2 = fmaf(W_fc2[2 * FC1N + f], v, wc2);
        }
        wc_sh[0][j] = wc0; wc_sh[1][j] = wc1; wc_sh[2][j] = wc2;
    }
    if (j < 3) {
        float s = 0.f;
        #pragma unroll 8
        for (int f = 0; f < FC1N; f++)
            s = fmaf(W_fc2[j * FC1N + f], b_fc1[f], s);
        bc_sh[j] = s + b_fc2[j];
    }

    // ---- initial hidden state lives in slot RING-1 (t = -1) ----
    h_ring[(RING - 1) * RPAD + j] = hidden[b * HH + j];
    __syncthreads();

    const int kg = j >> 5;        // FC k-group (0..3)
    const int tl = j & 31;        // FC local timestep
    float* outb = out + (size_t)b * TT * 3;

    float hv = 0.f;
    for (int t = 0; t < TT; t++) {
        // input projection (x broadcast from SMEM)
        const float xv0 = x_sh[3 * t + 0];
        const float xv1 = x_sh[3 * t + 1];
        const float xv2 = x_sh[3 * t + 2];
        float xp = fmaf(xv2, wih2, fmaf(xv1, wih1, fmaf(xv0, wih0, bias)));

        // 128-wide dot(W_j, h_prev): 4 chains x 16 packed FMAs (broadcast LDS)
        const ulonglong2* hp =
            (const ulonglong2*)(h_ring + ((t - 1) & (RING - 1)) * RPAD);
        unsigned long long a0 = 0ull, a1 = 0ull, a2 = 0ull, a3 = 0ull;
        #pragma unroll
        for (int i = 0; i < 16; i++) {
            ulonglong2 ha = hp[2 * i];
            ulonglong2 hb = hp[2 * i + 1];
            a0 = fma2(w[4 * i + 0], ha.x, a0);
            a1 = fma2(w[4 * i + 1], ha.y, a1);
            a2 = fma2(w[4 * i + 2], hb.x, a2);
            a3 = fma2(w[4 * i + 3], hb.y, a3);
        }
        unsigned long long s2 = add2(add2(a0, a1), add2(a2, a3));
        float2 f = unpack2(s2);

        hv = tanh_fast(xp + (f.x + f.y));
        h_ring[(t & (RING - 1)) * RPAD + j] = hv;
        __syncthreads();

        // ---- amortized FC head: every RING steps, drain slots 0..31 ----
        if ((t & (RING - 1)) == (RING - 1)) {
            const float4* h4 = (const float4*)(h_ring + tl * RPAD + kg * 32);
            const float4* w0 = (const float4*)(wc_sh[0] + kg * 32);
            const float4* w1 = (const float4*)(wc_sh[1] + kg * 32);
            const float4* w2 = (const float4*)(wc_sh[2] + kg * 32);
            float p0 = 0.f, p1 = 0.f, p2 = 0.f;
            #pragma unroll
            for (int i = 0; i < 8; i++) {
                float4 hq = h4[i];
                float4 wa = w0[i], wb = w1[i], wcc = w2[i];
                p0 = fmaf(hq.x, wa.x, fmaf(hq.y, wa.y, fmaf(hq.z, wa.z, fmaf(hq.w, wa.w, p0))));
                p1 = fmaf(hq.x, wb.x, fmaf(hq.y, wb.y, fmaf(hq.z, wb.z, fmaf(hq.w, wb.w, p1))));
                p2 = fmaf(hq.x, wcc.x, fmaf(hq.y, wcc.y, fmaf(hq.z, wcc.z, fmaf(hq.w, wcc.w, p2))));
            }
            part_sh[kg][tl * 3 + 0] = p0;
            part_sh[kg][tl * 3 + 1] = p1;
            part_sh[kg][tl * 3 + 2] = p2;
            __syncthreads();

            if (j < RING * 3) {
                float v = part_sh[0][j] + part_sh[1][j] +
                          part_sh[2][j] + part_sh[3][j] + bc_sh[j % 3];
                outb[(size_t)(t - (RING - 1)) * 3 + j] = v;   // 96 coalesced floats
            }
            // ring slot 0 is rewritten only after the next step's barrier;
            // partials are rewritten only after 32 more barriers. No extra sync.
        }
    }

    // final hidden state -> second output region
    out[(size_t)BB * TT * 3 + b * HH + j] = hv;
}

extern "C" void kernel_launch(void* const* d_in, const int* in_sizes, int n_in,
                              void* d_out, int out_size) {
    const float* x      = (const float*)d_in[0];
    const float* hidden = (const float*)d_in[1];
    const float* W_ih   = (const float*)d_in[2];
    const float* W_hh   = (const float*)d_in[3];
    const float* b_ih   = (const float*)d_in[4];
    const float* b_hh   = (const float*)d_in[5];
    const float* W_fc1  = (const float*)d_in[6];
    const float* b_fc1  = (const float*)d_in[7];
    const float* W_fc2  = (const float*)d_in[8];
    const float* b_fc2  = (const float*)d_in[9];
    float* out = (float*)d_out;

    rnn_fused_kernel<<<BB, HH>>>(x, hidden, W_ih, W_hh, b_ih, b_hh,
                                 W_fc1, b_fc1, W_fc2, b_fc2, out);
}

// round 17
// speedup vs baseline: 1.1019x; 1.0177x over previous
#include <cuda_runtime.h>

#define BB 256
#define TT 2048
#define HH 128
#define FC1N 64
#define RING 32          // ring depth (steps per FC chunk)
#define RPAD 132         // floats per ring row (16B-aligned, 4-way FC conflict)

__device__ __forceinline__ unsigned long long fma2(unsigned long long a,
                                                   unsigned long long b,
                                                   unsigned long long c) {
    unsigned long long d;
    asm("fma.rn.f32x2 %0, %1, %2, %3;" : "=l"(d) : "l"(a), "l"(b), "l"(c));
    return d;
}
__device__ __forceinline__ unsigned long long add2(unsigned long long a,
                                                   unsigned long long b) {
    unsigned long long d;
    asm("add.rn.f32x2 %0, %1, %2;" : "=l"(d) : "l"(a), "l"(b));
    return d;
}
__device__ __forceinline__ float2 unpack2(unsigned long long v) {
    float2 r;
    asm("mov.b64 {%0, %1}, %2;" : "=f"(r.x), "=f"(r.y) : "l"(v));
    return r;
}
__device__ __forceinline__ float tanh_fast(float x) {
    float y;
    asm("tanh.approx.f32 %0, %1;" : "=f"(y) : "f"(x));
    return y;
}

__global__ __launch_bounds__(128, 2)
void rnn_fused_kernel(const float* __restrict__ x,
                      const float* __restrict__ hidden,
                      const float* __restrict__ W_ih,
                      const float* __restrict__ W_hh,
                      const float* __restrict__ b_ih,
                      const float* __restrict__ b_hh,
                      const float* __restrict__ W_fc1,
                      const float* __restrict__ b_fc1,
                      const float* __restrict__ W_fc2,
                      const float* __restrict__ b_fc2,
                      float* __restrict__ out)
{
    __shared__ __align__(16) float x_sh[TT * 3];            // 24 KB
    __shared__ __align__(16) float h_ring[RING * RPAD];     // 16.5 KB
    __shared__ __align__(16) float wc_sh[3][HH];            // collapsed fc2@fc1
    __shared__ float part_sh[4][RING * 3];                  // FC partials
    __shared__ float bc_sh[3];

    const int b = blockIdx.x;
    const int j = threadIdx.x;          // hidden unit owned by this thread

    // ---- preload x[b] into SMEM (coalesced float4, 12 iters) ----
    {
        const float4* xg = (const float4*)(x + (size_t)b * TT * 3);
        float4* xs = (float4*)x_sh;
        #pragma unroll
        for (int i = 0; i < (TT * 3 / 4) / HH; i++)
            xs[i * HH + j] = xg[i * HH + j];
    }

    // ---- W_hh row j into registers as packed f32x2 (64 ull regs) ----
    unsigned long long w[HH / 2];
    {
        const unsigned long long* wg = (const unsigned long long*)(W_hh + j * HH);
        #pragma unroll
        for (int i = 0; i < HH / 2; i++) w[i] = wg[i];
    }

    const float wih0 = W_ih[j * 3 + 0];
    const float wih1 = W_ih[j * 3 + 1];
    const float wih2 = W_ih[j * 3 + 2];
    const float bias = b_ih[j] + b_hh[j];

    // ---- collapse FC head: wc[o][j] = sum_f W_fc2[o][f] * W_fc1[f][j] ----
    {
        float wc0 = 0.f, wc1 = 0.f, wc2 = 0.f;
        #pragma unroll 4
        for (int f = 0; f < FC1N; f++) {
            float v = W_fc1[f * HH + j];
            wc0 = fmaf(W_fc2[0 * FC1N + f], v, wc0);
            wc1 = fmaf(W_fc2[1 * FC1N + f], v, wc1);
            wc2 = fmaf(W_fc2[2 * FC1N + f], v, wc2);
        }
        wc_sh[0][j] = wc0; wc_sh[1][j] = wc1; wc_sh[2][j] = wc2;
    }
    if (j < 3) {
        float s = 0.f;
        #pragma unroll 8
        for (int f = 0; f < FC1N; f++)
            s = fmaf(W_fc2[j * FC1N + f], b_fc1[f], s);
        bc_sh[j] = s + b_fc2[j];
    }

    // ---- initial hidden state lives in slot RING-1 (t = -1) ----
    h_ring[(RING - 1) * RPAD + j] = hidden[b * HH + j];
    __syncthreads();

    const int kg = j >> 5;        // FC k-group (0..3)
    const int tl = j & 31;        // FC local timestep
    float* outb = out + (size_t)b * TT * 3;

    float hv = 0.f;
    const float* xs = x_sh;       // walks forward 3 floats per step

    for (int tc = 0; tc < TT / RING; tc++) {
        // ring pointers: rd starts at last chunk's final slot, wr at slot 0
        const float* rd = h_ring + (RING - 1) * RPAD;
        float*       wr = h_ring;

        #pragma unroll 1
        for (int ts = 0; ts < RING; ts++) {
            // input projection (x broadcast from SMEM)
            const float xv0 = xs[0];
            const float xv1 = xs[1];
            const float xv2 = xs[2];
            float xp = fmaf(xv2, wih2, fmaf(xv1, wih1, fmaf(xv0, wih0, bias)));

            // 128-wide dot(W_j, h_prev): 4 chains x 16 packed FMAs
            const ulonglong2* hp = (const ulonglong2*)rd;
            unsigned long long a0 = 0ull, a1 = 0ull, a2 = 0ull, a3 = 0ull;
            #pragma unroll
            for (int i = 0; i < 16; i++) {
                ulonglong2 ha = hp[2 * i];
                ulonglong2 hb = hp[2 * i + 1];
                a0 = fma2(w[4 * i + 0], ha.x, a0);
                a1 = fma2(w[4 * i + 1], ha.y, a1);
                a2 = fma2(w[4 * i + 2], hb.x, a2);
                a3 = fma2(w[4 * i + 3], hb.y, a3);
            }
            unsigned long long s2 = add2(add2(a0, a1), add2(a2, a3));
            float2 f = unpack2(s2);

            hv = tanh_fast(xp + (f.x + f.y));
            wr[j] = hv;
            __syncthreads();

            rd = wr;          // next step reads what we just wrote
            wr += RPAD;       // next slot (never wraps inside the chunk)
            xs += 3;
        }

        // ---- FC drain: slots 0..31 -> 96 outputs for this chunk ----
        {
            const float4* h4 = (const float4*)(h_ring + tl * RPAD + kg * 32);
            const float4* w0 = (const float4*)(wc_sh[0] + kg * 32);
            const float4* w1 = (const float4*)(wc_sh[1] + kg * 32);
            const float4* w2 = (const float4*)(wc_sh[2] + kg * 32);
            float p0 = 0.f, p1 = 0.f, p2 = 0.f;
            #pragma unroll
            for (int i = 0; i < 8; i++) {
                float4 hq = h4[i];
                float4 wa = w0[i], wb = w1[i], wcc = w2[i];
                p0 = fmaf(hq.x, wa.x, fmaf(hq.y, wa.y, fmaf(hq.z, wa.z, fmaf(hq.w, wa.w, p0))));
                p1 = fmaf(hq.x, wb.x, fmaf(hq.y, wb.y, fmaf(hq.z, wb.z, fmaf(hq.w, wb.w, p1))));
                p2 = fmaf(hq.x, wcc.x, fmaf(hq.y, wcc.y, fmaf(hq.z, wcc.z, fmaf(hq.w, wcc.w, p2))));
            }
            part_sh[kg][tl * 3 + 0] = p0;
            part_sh[kg][tl * 3 + 1] = p1;
            part_sh[kg][tl * 3 + 2] = p2;
            __syncthreads();

            if (j < RING * 3) {
                float v = part_sh[0][j] + part_sh[1][j] +
                          part_sh[2][j] + part_sh[3][j] + bc_sh[j % 3];
                outb[(size_t)tc * (RING * 3) + j] = v;   // 96 coalesced floats
            }
            // ring slot 0 is rewritten only after the next step's barrier;
            // partials are rewritten only after 32 more barriers. No extra sync.
        }
    }

    // final hidden state -> second output region
    out[(size_t)BB * TT * 3 + b * HH + j] = hv;
}

extern "C" void kernel_launch(void* const* d_in, const int* in_sizes, int n_in,
                              void* d_out, int out_size) {
    const float* x      = (const float*)d_in[0];
    const float* hidden = (const float*)d_in[1];
    const float* W_ih   = (const float*)d_in[2];
    const float* W_hh   = (const float*)d_in[3];
    const float* b_ih   = (const float*)d_in[4];
    const float* b_hh   = (const float*)d_in[5];
    const float* W_fc1  = (const float*)d_in[6];
    const float* b_fc1  = (const float*)d_in[7];
    const float* W_fc2  = (const float*)d_in[8];
    const float* b_fc2  = (const float*)d_in[9];
    float* out = (float*)d_out;

    rnn_fused_kernel<<<BB, HH>>>(x, hidden, W_ih, W_hh, b_ih, b_hh,
                                 W_fc1, b_fc1, W_fc2, b_fc2, out);
}